// round 13
// baseline (speedup 1.0000x reference)
#include <cuda_runtime.h>
#include <cuda_fp16.h>
#include <mma.h>
#include <math.h>
#include <cstdint>

using namespace nvcuda;

#define NB   8
#define NLQ  32
#define NLKV 4096
#define NH   16
#define ND   64
#define NHS  1024
#define MKV  (NB*NLKV)      /* 32768 */
#define MQ   (NB*NLQ)       /* 256   */
#define MR   (NB*NH*NLQ)    /* 4096 score rows */
#define QSPL 8              /* k-split for qproj */
#define VSPL 4              /* k-split for vproj */
#define OSPL 8              /* k-split for oproj */

// ---------------- scratch (device globals) ----------------------------------
__device__ __align__(256) __half g_Xh [MKV*NHS];         // encoder fp16 (64MB)
__device__ __align__(256) __half g_Qt [MR*NHS];          // q~ fp16, 0.125 folded
__device__ __align__(256) float  g_S  [(size_t)MR*NLKV]; // scores fp32 (64MB); later Y
__device__ __align__(256) __half g_P  [(size_t)MR*NLKV]; // softmax fp16 (32MB)
__device__ __align__(256) float  g_qpart[QSPL*MQ*NHS];   // qproj partials / vproj partials
__device__ __align__(256) float  g_opart[OSPL*MQ*NHS];   // oproj partials

// ---------------- cp.async helpers ------------------------------------------
__device__ __forceinline__ uint32_t smem_u32(const void* p) {
    uint32_t a;
    asm("{ .reg .u64 t; cvta.to.shared.u64 t, %1; cvt.u32.u64 %0, t; }"
        : "=r"(a) : "l"(p));
    return a;
}
__device__ __forceinline__ void cp_async16(uint32_t dst, const void* src) {
    asm volatile("cp.async.cg.shared.global [%0], [%1], 16;" :: "r"(dst), "l"(src));
}
#define CP_COMMIT() asm volatile("cp.async.commit_group;" ::: "memory")
#define CP_WAIT1()  asm volatile("cp.async.wait_group 1;" ::: "memory")
#define CP_WAIT0()  asm volatile("cp.async.wait_group 0;" ::: "memory")

// ---------------- prep: encoder fp32->fp16 AND qproj partials ------------------
__global__ void __launch_bounds__(256) prep(
    const float* __restrict__ enc, const float* __restrict__ hidden,
    const float* __restrict__ Wq)
{
    int bx = blockIdx.x;
    int t = threadIdx.x;
    if (bx >= 256) {
        int i = (bx - 256) * 256 + t;
        float4 v = reinterpret_cast<const float4*>(enc)[i];
        reinterpret_cast<__half2*>(g_Xh)[2*i+0] = __floats2half2_rn(v.x, v.y);
        reinterpret_cast<__half2*>(g_Xh)[2*i+1] = __floats2half2_rn(v.z, v.w);
        return;
    }
    int c0 = (bx & 3) * 256, r0 = ((bx >> 2) & 7) * 32, ks = bx >> 5;   // ks 0..7
    __shared__ float xs[32][128];
    for (int i = t; i < 32 * 128; i += 256)
        xs[i >> 7][i & 127] = hidden[(size_t)(r0 + (i >> 7)) * NHS + ks * 128 + (i & 127)];
    __syncthreads();
    float acc[32];
#pragma unroll
    for (int r = 0; r < 32; r++) acc[r] = 0.f;
    int c = c0 + t;
    const float* Wc = Wq + (size_t)(ks * 128) * NHS + c;
    for (int k = 0; k < 128; k += 4) {
        float w0 = Wc[(size_t)(k+0) * NHS];
        float w1 = Wc[(size_t)(k+1) * NHS];
        float w2 = Wc[(size_t)(k+2) * NHS];
        float w3 = Wc[(size_t)(k+3) * NHS];
#pragma unroll
        for (int r = 0; r < 32; r++) {
            float4 xv = *reinterpret_cast<const float4*>(&xs[r][k]);
            acc[r] += xv.x * w0 + xv.y * w1 + xv.z * w2 + xv.w * w3;
        }
    }
#pragma unroll
    for (int r = 0; r < 32; r++)
        g_qpart[((size_t)ks * MQ + r0 + r) * NHS + c] = acc[r];
}

// ---------------- qtilde (fused qproj-reduce + RoPE + wmma) ---------------------
// grid (128 bh, 8 c-chunks), 128 threads
__global__ void __launch_bounds__(128) qtilde(
    const float* __restrict__ Wk, const int* __restrict__ pos32)
{
    int bh = blockIdx.x, b = bh >> 4, h = bh & 15;
    int c0 = blockIdx.y * 128;
    __shared__ float qsum[32][68];
    __shared__ __align__(16) __half qh[32][72];
    __shared__ __align__(16) __half wk[128][72];
    __shared__ __align__(16) float  outs[32][132];
    __shared__ int is64;
    int t = threadIdx.x, wid = t >> 5;

    if (t == 0) {
        int f = 0;
        for (int i = 1; i < 256; i += 2) f |= pos32[i];
        is64 = (f == 0) ? 1 : 0;
    }
    for (int i = t; i < 32 * 64; i += 128) {
        int q = i >> 6, d = i & 63;
        float s = 0.f;
#pragma unroll
        for (int ks = 0; ks < QSPL; ks++)
            s += g_qpart[((size_t)ks * MQ + b * NLQ + q) * NHS + h * ND + d];
        qsum[q][d] = s;
    }
    for (int i = t; i < 128 * 64; i += 128) {
        int r = i >> 6, d = i & 63;
        wk[r][d] = __float2half_rn(Wk[(size_t)(c0 + r) * NHS + h * ND + d]);
    }
    __syncthreads();
    for (int i = t; i < 32 * 64; i += 128) {
        int q = i >> 6, d = i & 63;
        int row = b * NLQ + q;
        int p = is64 ? pos32[2 * row] : pos32[row];
        int fi = d & 31;
        float invf = (float)pow(10000.0, -(double)fi / 32.0);
        float sv, cv;
        sincosf((float)p * invf, &sv, &cv);
        float rot = (d & 32) ? qsum[q][d - 32] : -qsum[q][d + 32];
        qh[q][d] = __float2half_rn((qsum[q][d] * cv + rot * sv) * 0.125f);
    }
    __syncthreads();

    wmma::fragment<wmma::accumulator, 16, 16, 16, float> cf[2][2];
#pragma unroll
    for (int i = 0; i < 2; i++)
#pragma unroll
        for (int j = 0; j < 2; j++) wmma::fill_fragment(cf[i][j], 0.f);
#pragma unroll
    for (int kk = 0; kk < 64; kk += 16) {
        wmma::fragment<wmma::matrix_a, 16, 16, 16, __half, wmma::row_major> af[2];
        wmma::load_matrix_sync(af[0], &qh[0][kk], 72);
        wmma::load_matrix_sync(af[1], &qh[16][kk], 72);
#pragma unroll
        for (int j = 0; j < 2; j++) {
            wmma::fragment<wmma::matrix_b, 16, 16, 16, __half, wmma::col_major> bf;
            wmma::load_matrix_sync(bf, &wk[wid * 32 + j * 16][kk], 72);
            wmma::mma_sync(cf[0][j], af[0], bf, cf[0][j]);
            wmma::mma_sync(cf[1][j], af[1], bf, cf[1][j]);
        }
    }
#pragma unroll
    for (int i = 0; i < 2; i++)
#pragma unroll
        for (int j = 0; j < 2; j++)
            wmma::store_matrix_sync(&outs[i * 16][wid * 32 + j * 16], cf[i][j], 132,
                                    wmma::mem_row_major);
    __syncthreads();
    for (int i = t; i < 32 * 128; i += 128) {
        int q = i >> 7, cl = i & 127;
        g_Qt[(size_t)(bh * NLQ + q) * NHS + c0 + cl] = __float2half_rn(outs[q][cl]);
    }
}

// ---------------- S = q~ @ X^T : wmma 64x64 tiles, 3-stage, fp32 out ------------
#define BM 128
#define BN 128
#define BK 32
#define LDK 40
#define SG_AS (BM * LDK)
#define SG_BS (BN * LDK)
#define SG_SMEM (3 * (SG_AS + SG_BS) * 2)   /* 61440 B */
__global__ void __launch_bounds__(128) sgemm()
{
    extern __shared__ __align__(16) __half dsm[];
    __half* As = dsm;
    __half* Bs = dsm + 3 * SG_AS;

    int b = blockIdx.z;
    int n0 = blockIdx.x * BN, m0 = blockIdx.y * BM;
    const __half* Ab = g_Qt + (size_t)b * 512 * NHS;
    const __half* Xb = g_Xh + (size_t)b * NLKV * NHS;
    float* Cb = g_S + (size_t)b * 512 * NLKV;

    int t = threadIdx.x, wid = t >> 5;
    int wm = wid & 1, wn = wid >> 1;

    wmma::fragment<wmma::accumulator, 16, 16, 16, float> cf[4][4];
#pragma unroll
    for (int i = 0; i < 4; i++)
#pragma unroll
        for (int j = 0; j < 4; j++) wmma::fill_fragment(cf[i][j], 0.f);

    auto load_stage = [&](int it, int buf) {
        int k0 = it * BK;
        __half* Ad = As + buf * SG_AS;
        __half* Bd = Bs + buf * SG_BS;
#pragma unroll
        for (int ch = t; ch < 512; ch += 128) {
            int r = ch >> 2, c = ch & 3;
            cp_async16(smem_u32(Ad + r * LDK + c * 8),
                       &Ab[(size_t)(m0 + r) * NHS + k0 + c * 8]);
        }
#pragma unroll
        for (int ch = t; ch < 512; ch += 128) {
            int r = ch >> 2, c = ch & 3;
            cp_async16(smem_u32(Bd + r * LDK + c * 8),
                       &Xb[(size_t)(n0 + r) * NHS + k0 + c * 8]);
        }
        CP_COMMIT();
    };

    const int NIT = NHS / BK;   // 32
    load_stage(0, 0);
    load_stage(1, 1);
    int buf = 0;
    for (int it = 0; it < NIT; it++) {
        CP_WAIT1();
        __syncthreads();
        if (it + 2 < NIT) {
            int nb = buf + 2; if (nb >= 3) nb -= 3;
            load_stage(it + 2, nb);
        }
        const __half* Ad = As + buf * SG_AS;
        const __half* Bd = Bs + buf * SG_BS;
#pragma unroll
        for (int kk = 0; kk < BK; kk += 16) {
            wmma::fragment<wmma::matrix_a, 16, 16, 16, __half, wmma::row_major> af[4];
#pragma unroll
            for (int i = 0; i < 4; i++)
                wmma::load_matrix_sync(af[i], Ad + (wm * 64 + i * 16) * LDK + kk, LDK);
#pragma unroll
            for (int j = 0; j < 4; j++) {
                wmma::fragment<wmma::matrix_b, 16, 16, 16, __half, wmma::col_major> bf;
                wmma::load_matrix_sync(bf, Bd + (wn * 64 + j * 16) * LDK + kk, LDK);
#pragma unroll
                for (int i = 0; i < 4; i++)
                    wmma::mma_sync(cf[i][j], af[i], bf, cf[i][j]);
            }
        }
        if (++buf == 3) buf = 0;
    }
#pragma unroll
    for (int i = 0; i < 4; i++)
#pragma unroll
        for (int j = 0; j < 4; j++)
            wmma::store_matrix_sync(
                &Cb[(size_t)(m0 + wm * 64 + i * 16) * NLKV + n0 + wn * 64 + j * 16],
                cf[i][j], NLKV, wmma::mem_row_major);
}

// ---------------- softmax rows of 4096: fp32 g_S -> fp16 g_P --------------------
__global__ void __launch_bounds__(256) softmax_rows()
{
    size_t m = blockIdx.x;
    const float4* row = reinterpret_cast<const float4*>(g_S + m * NLKV);
    __half2* prow = reinterpret_cast<__half2*>(g_P + m * NLKV);
    int t = threadIdx.x;
    __shared__ float red[8];

    float4 x[4];
    float mx = -1e30f;
#pragma unroll
    for (int i = 0; i < 4; i++) {
        x[i] = row[i * 256 + t];
        mx = fmaxf(fmaxf(fmaxf(mx, x[i].x), fmaxf(x[i].y, x[i].z)), x[i].w);
    }
#pragma unroll
    for (int o = 16; o > 0; o >>= 1)
        mx = fmaxf(mx, __shfl_xor_sync(0xffffffffu, mx, o));
    if ((t & 31) == 0) red[t >> 5] = mx;
    __syncthreads();
    if (t < 8) {
        float v = red[t];
#pragma unroll
        for (int o = 4; o > 0; o >>= 1) v = fmaxf(v, __shfl_xor_sync(0xffu, v, o));
        red[t] = v;
    }
    __syncthreads();
    mx = red[0];

    float s = 0.f;
#pragma unroll
    for (int i = 0; i < 4; i++) {
        x[i].x = __expf(x[i].x - mx); x[i].y = __expf(x[i].y - mx);
        x[i].z = __expf(x[i].z - mx); x[i].w = __expf(x[i].w - mx);
        s += (x[i].x + x[i].y) + (x[i].z + x[i].w);
    }
#pragma unroll
    for (int o = 16; o > 0; o >>= 1)
        s += __shfl_xor_sync(0xffffffffu, s, o);
    __syncthreads();
    if ((t & 31) == 0) red[t >> 5] = s;
    __syncthreads();
    if (t < 8) {
        float v = red[t];
#pragma unroll
        for (int o = 4; o > 0; o >>= 1) v += __shfl_xor_sync(0xffu, v, o);
        red[t] = v;
    }
    __syncthreads();
    float inv = 1.f / red[0];
#pragma unroll
    for (int i = 0; i < 4; i++) {
        prow[(i * 256 + t) * 2 + 0] = __floats2half2_rn(x[i].x * inv, x[i].y * inv);
        prow[(i * 256 + t) * 2 + 1] = __floats2half2_rn(x[i].z * inv, x[i].w * inv);
    }
}

// ---------------- Y = P @ X -> g_S (reused), wmma 64x64 tiles, 3-stage ----------
#define LDN 136
#define YG_AS (BM * LDK)
#define YG_BS (BK * LDN)
#define YG_SMEM (3 * (YG_AS + YG_BS) * 2)   /* 56832 B */
__global__ void __launch_bounds__(128) ygemm()
{
    extern __shared__ __align__(16) __half dsm[];
    __half* As = dsm;
    __half* Bs = dsm + 3 * YG_AS;

    int b = blockIdx.z;
    int n0 = blockIdx.x * BN, m0 = blockIdx.y * BM;
    const __half* Ab = g_P + (size_t)b * 512 * NLKV;
    const __half* Xb = g_Xh + (size_t)b * NLKV * NHS;
    float* Cb = g_S + (size_t)b * 512 * NHS;    // Y stored in g_S

    int t = threadIdx.x, wid = t >> 5;
    int wm = wid & 1, wn = wid >> 1;

    wmma::fragment<wmma::accumulator, 16, 16, 16, float> cf[4][4];
#pragma unroll
    for (int i = 0; i < 4; i++)
#pragma unroll
        for (int j = 0; j < 4; j++) wmma::fill_fragment(cf[i][j], 0.f);

    auto load_stage = [&](int it, int buf) {
        int k0 = it * BK;
        __half* Ad = As + buf * YG_AS;
        __half* Bd = Bs + buf * YG_BS;
#pragma unroll
        for (int ch = t; ch < 512; ch += 128) {
            int r = ch >> 2, c = ch & 3;
            cp_async16(smem_u32(Ad + r * LDK + c * 8),
                       &Ab[(size_t)(m0 + r) * NLKV + k0 + c * 8]);
        }
#pragma unroll
        for (int ch = t; ch < 512; ch += 128) {
            int r = ch >> 4, c = ch & 15;
            cp_async16(smem_u32(Bd + r * LDN + c * 8),
                       &Xb[(size_t)(k0 + r) * NHS + n0 + c * 8]);
        }
        CP_COMMIT();
    };

    const int NIT = NLKV / BK;   // 128
    load_stage(0, 0);
    load_stage(1, 1);
    int buf = 0;
    for (int it = 0; it < NIT; it++) {
        CP_WAIT1();
        __syncthreads();
        if (it + 2 < NIT) {
            int nb = buf + 2; if (nb >= 3) nb -= 3;
            load_stage(it + 2, nb);
        }
        const __half* Ad = As + buf * YG_AS;
        const __half* Bd = Bs + buf * YG_BS;
#pragma unroll
        for (int kk = 0; kk < BK; kk += 16) {
            wmma::fragment<wmma::matrix_a, 16, 16, 16, __half, wmma::row_major> af[4];
#pragma unroll
            for (int i = 0; i < 4; i++)
                wmma::load_matrix_sync(af[i], Ad + (wm * 64 + i * 16) * LDK + kk, LDK);
#pragma unroll
            for (int j = 0; j < 4; j++) {
                wmma::fragment<wmma::matrix_b, 16, 16, 16, __half, wmma::row_major> bf;
                wmma::load_matrix_sync(bf, Bd + kk * LDN + wn * 64 + j * 16, LDN);
#pragma unroll
                for (int i = 0; i < 4; i++)
                    wmma::mma_sync(cf[i][j], af[i], bf, cf[i][j]);
            }
        }
        if (++buf == 3) buf = 0;
    }
#pragma unroll
    for (int i = 0; i < 4; i++)
#pragma unroll
        for (int j = 0; j < 4; j++)
            wmma::store_matrix_sync(
                &Cb[(size_t)(m0 + wm * 64 + i * 16) * NHS + n0 + wn * 64 + j * 16],
                cf[i][j], NHS, wmma::mem_row_major);
}

// ---------------- vproj partials (reads Y from g_S) ------------------------------
__global__ void __launch_bounds__(256) vproj_part(const float* __restrict__ Wv)
{
    int bh = blockIdx.x, b = bh >> 4, h = bh & 15;
    int ks = blockIdx.y;
    __shared__ float wvs[128][68];
    __shared__ float ys[32][132];
    int t = threadIdx.x;
    int d = t & 63, qg = t >> 6;
    float acc[8];
#pragma unroll
    for (int j = 0; j < 8; j++) acc[j] = 0.f;

#pragma unroll
    for (int half = 0; half < 2; half++) {
        int c0 = ks * 256 + half * 128;
        __syncthreads();
        for (int i = t; i < 128 * 64; i += 256) {
            int r = i >> 6, dd = i & 63;
            wvs[r][dd] = Wv[(size_t)(c0 + r) * NHS + h * ND + dd];
        }
        for (int i = t; i < 32 * 128; i += 256) {
            int q = i >> 7, cl = i & 127;
            ys[q][cl] = g_S[(size_t)(bh * NLQ + q) * NHS + c0 + cl];
        }
        __syncthreads();
#pragma unroll 4
        for (int c = 0; c < 128; c++) {
            float w = wvs[c][d];
#pragma unroll
            for (int j = 0; j < 8; j++) acc[j] += ys[qg * 8 + j][c] * w;
        }
    }
#pragma unroll
    for (int j = 0; j < 8; j++)
        g_qpart[((size_t)ks * MQ + b * NLQ + qg * 8 + j) * NHS + h * ND + d] = acc[j];
}

// ---------------- oproj partial (sums vproj partials), k-split 8 ----------------
__global__ void __launch_bounds__(256) oproj_part(const float* __restrict__ W)
{
    int c0 = blockIdx.x * 256, r0 = blockIdx.y * 32, ks = blockIdx.z;
    __shared__ float xs[32][128];
    int t = threadIdx.x;
    for (int i = t; i < 32 * 128; i += 256) {
        int r = i >> 7, kk = i & 127;
        size_t base = (size_t)(r0 + r) * NHS + ks * 128 + kk;
        float s = 0.f;
#pragma unroll
        for (int s2 = 0; s2 < VSPL; s2++)
            s += g_qpart[(size_t)s2 * MQ * NHS + base];
        xs[r][kk] = s;
    }
    __syncthreads();
    float acc[32];
#pragma unroll
    for (int r = 0; r < 32; r++) acc[r] = 0.f;
    int c = c0 + t;
    const float* Wc = W + (size_t)(ks * 128) * NHS + c;
    for (int k = 0; k < 128; k += 4) {
        float w0 = Wc[(size_t)(k+0) * NHS];
        float w1 = Wc[(size_t)(k+1) * NHS];
        float w2 = Wc[(size_t)(k+2) * NHS];
        float w3 = Wc[(size_t)(k+3) * NHS];
#pragma unroll
        for (int r = 0; r < 32; r++) {
            float4 xv = *reinterpret_cast<const float4*>(&xs[r][k]);
            acc[r] += xv.x * w0 + xv.y * w1 + xv.z * w2 + xv.w * w3;
        }
    }
#pragma unroll
    for (int r = 0; r < 32; r++)
        g_opart[((size_t)ks * MQ + r0 + r) * NHS + c] = acc[r];
}

__global__ void __launch_bounds__(256) oreduce(float* __restrict__ Y)
{
    int i = blockIdx.x * 256 + threadIdx.x;
    float s = 0.f;
#pragma unroll
    for (int ks = 0; ks < OSPL; ks++)
        s += g_opart[(size_t)ks * MQ * NHS + i];
    Y[i] = s;
}

// ================= launcher =======================================================
extern "C" void kernel_launch(void* const* d_in, const int* in_sizes, int n_in,
                              void* d_out, int out_size)
{
    const float* hidden = (const float*)d_in[0];
    const float* enc    = (const float*)d_in[1];
    const int*   pos32  = (const int*)d_in[2];
    const float* Wq     = (const float*)d_in[3];
    const float* Wk     = (const float*)d_in[4];
    const float* Wv     = (const float*)d_in[5];
    const float* Wo     = (const float*)d_in[6];
    float*       out    = (float*)d_out;

    cudaFuncSetAttribute(sgemm, cudaFuncAttributeMaxDynamicSharedMemorySize, SG_SMEM);
    cudaFuncSetAttribute(ygemm, cudaFuncAttributeMaxDynamicSharedMemorySize, YG_SMEM);

    // 1) fused: encoder->fp16 + qproj partials (k-split 8)
    prep<<<256 + MKV * NHS / 4 / 256, 256>>>(enc, hidden, Wq);

    // 2) fused reduce+RoPE+Wk-fold
    qtilde<<<dim3(NB * NH, 8), 128>>>(Wk, pos32);

    // 3) S = q~ @ X^T -> fp32 g_S
    sgemm<<<dim3(NLKV / BN, 4, NB), 128, SG_SMEM>>>();

    // 4) softmax: fp32 -> fp16 g_P
    softmax_rows<<<MR, 256>>>();

    // 5) Y = P @ X -> g_S
    ygemm<<<dim3(NHS / BN, 4, NB), 128, YG_SMEM>>>();

    // 6) fold Wv (partials into g_qpart)
    vproj_part<<<dim3(NB * NH, VSPL), 256>>>(Wv);

    // 7) output projection (k-split 8)
    oproj_part<<<dim3(4, 8, OSPL), 256>>>(Wo);
    oreduce<<<(MQ * NHS) / 256, 256>>>(out);
}

// round 14
// speedup vs baseline: 1.1249x; 1.1249x over previous
#include <cuda_runtime.h>
#include <cuda_fp16.h>
#include <mma.h>
#include <math.h>
#include <cstdint>

using namespace nvcuda;

#define NB   8
#define NLQ  32
#define NLKV 4096
#define NH   16
#define ND   64
#define NHS  1024
#define MKV  (NB*NLKV)      /* 32768 */
#define MQ   (NB*NLQ)       /* 256   */
#define MR   (NB*NH*NLQ)    /* 4096 score rows */
#define QSPL 8              /* k-split for qproj */
#define VSPL 4              /* k-split for vproj */
#define OSPL 8              /* k-split for oproj */

// ---------------- scratch (device globals) ----------------------------------
__device__ __align__(256) __half g_Xh [MKV*NHS];         // encoder fp16 (64MB)
__device__ __align__(256) float  g_Qp [MQ*NHS];          // Q + RoPE (fp32)
__device__ __align__(256) __half g_Qt [MR*NHS];          // q~ fp16, 0.125 folded
__device__ __align__(256) float  g_S  [(size_t)MR*NLKV]; // scores fp32; later Y
__device__ __align__(256) __half g_P  [(size_t)MR*NLKV]; // softmax fp16 (32MB)
__device__ __align__(256) float  g_qpart[QSPL*MQ*NHS];   // qproj partials / vproj partials
__device__ __align__(256) float  g_opart[OSPL*MQ*NHS];   // oproj partials

// ---------------- cp.async helpers ------------------------------------------
__device__ __forceinline__ uint32_t smem_u32(const void* p) {
    uint32_t a;
    asm("{ .reg .u64 t; cvta.to.shared.u64 t, %1; cvt.u32.u64 %0, t; }"
        : "=r"(a) : "l"(p));
    return a;
}
__device__ __forceinline__ void cp_async16(uint32_t dst, const void* src) {
    asm volatile("cp.async.cg.shared.global [%0], [%1], 16;" :: "r"(dst), "l"(src));
}
#define CP_COMMIT() asm volatile("cp.async.commit_group;" ::: "memory")
#define CP_WAIT1()  asm volatile("cp.async.wait_group 1;" ::: "memory")
#define CP_WAIT0()  asm volatile("cp.async.wait_group 0;" ::: "memory")

// ---------------- prep: encoder fp32->fp16 AND qproj partials ------------------
// blocks [0,256): qproj partial (k-range 128); blocks [256, 256+16384): cvt (2 f4/thr)
__global__ void __launch_bounds__(256) prep(
    const float* __restrict__ enc, const float* __restrict__ hidden,
    const float* __restrict__ Wq)
{
    int bx = blockIdx.x;
    int t = threadIdx.x;
    if (bx >= 256) {
        int base = (bx - 256) * 512 + t;
#pragma unroll
        for (int u = 0; u < 2; u++) {
            int i = base + u * 256;
            float4 v = reinterpret_cast<const float4*>(enc)[i];
            reinterpret_cast<__half2*>(g_Xh)[2*i+0] = __floats2half2_rn(v.x, v.y);
            reinterpret_cast<__half2*>(g_Xh)[2*i+1] = __floats2half2_rn(v.z, v.w);
        }
        return;
    }
    int c0 = (bx & 3) * 256, r0 = ((bx >> 2) & 7) * 32, ks = bx >> 5;   // ks 0..7
    __shared__ float xs[32][128];
    for (int i = t; i < 32 * 128; i += 256)
        xs[i >> 7][i & 127] = hidden[(size_t)(r0 + (i >> 7)) * NHS + ks * 128 + (i & 127)];
    __syncthreads();
    float acc[32];
#pragma unroll
    for (int r = 0; r < 32; r++) acc[r] = 0.f;
    int c = c0 + t;
    const float* Wc = Wq + (size_t)(ks * 128) * NHS + c;
    for (int k = 0; k < 128; k += 4) {
        float w0 = Wc[(size_t)(k+0) * NHS];
        float w1 = Wc[(size_t)(k+1) * NHS];
        float w2 = Wc[(size_t)(k+2) * NHS];
        float w3 = Wc[(size_t)(k+3) * NHS];
#pragma unroll
        for (int r = 0; r < 32; r++) {
            float4 xv = *reinterpret_cast<const float4*>(&xs[r][k]);
            acc[r] += xv.x * w0 + xv.y * w1 + xv.z * w2 + xv.w * w3;
        }
    }
#pragma unroll
    for (int r = 0; r < 32; r++)
        g_qpart[((size_t)ks * MQ + r0 + r) * NHS + c] = acc[r];
}

// ---------------- reduce + RoPE -> g_Qp ----------------------------------------
__global__ void __launch_bounds__(256) rope_reduce(const int* __restrict__ pos32)
{
    __shared__ float qrow[NHS];
    __shared__ int is64;
    int row = blockIdx.x, t = threadIdx.x;
    if (t == 0) {
        int f = 0;
        for (int i = 1; i < 256; i += 2) f |= pos32[i];
        is64 = (f == 0) ? 1 : 0;
    }
#pragma unroll
    for (int j = 0; j < 4; j++) {
        int c = j * 256 + t;
        float s = 0.f;
#pragma unroll
        for (int ks = 0; ks < QSPL; ks++)
            s += g_qpart[((size_t)ks * MQ + row) * NHS + c];
        qrow[c] = s;
    }
    __syncthreads();
    int p = is64 ? pos32[2 * row] : pos32[row];
    float pf = (float)p;
#pragma unroll
    for (int j = 0; j < 4; j++) {
        int c = j * 256 + t;
        int d = c & 63, fi = d & 31;
        float invf = (float)pow(10000.0, -(double)fi / 32.0);
        float sv, cv;
        sincosf(pf * invf, &sv, &cv);
        float rot = (d & 32) ? qrow[c - 32] : -qrow[c + 32];
        g_Qp[(size_t)row * NHS + c] = qrow[c] * cv + rot * sv;
    }
}

// ---------------- q~ via wmma: [32 x 128] = q[32x64] @ WkT[64x128] --------------
// grid (128 bh, 8 c-chunks), 128 threads
__global__ void __launch_bounds__(128) qtilde(const float* __restrict__ Wk)
{
    int bh = blockIdx.x, b = bh >> 4, h = bh & 15;
    int c0 = blockIdx.y * 128;
    __shared__ __align__(16) __half qh[32][72];
    __shared__ __align__(16) __half wk[128][72];
    __shared__ __align__(16) float  outs[32][132];
    int t = threadIdx.x, wid = t >> 5;

    for (int i = t; i < 32 * 64; i += 128) {
        int q = i >> 6, d = i & 63;
        qh[q][d] = __float2half_rn(g_Qp[(size_t)(b * NLQ + q) * NHS + h * ND + d] * 0.125f);
    }
    for (int i = t; i < 128 * 64; i += 128) {
        int r = i >> 6, d = i & 63;
        wk[r][d] = __float2half_rn(Wk[(size_t)(c0 + r) * NHS + h * ND + d]);
    }
    __syncthreads();

    wmma::fragment<wmma::accumulator, 16, 16, 16, float> cf[2][2];
#pragma unroll
    for (int i = 0; i < 2; i++)
#pragma unroll
        for (int j = 0; j < 2; j++) wmma::fill_fragment(cf[i][j], 0.f);
#pragma unroll
    for (int kk = 0; kk < 64; kk += 16) {
        wmma::fragment<wmma::matrix_a, 16, 16, 16, __half, wmma::row_major> af[2];
        wmma::load_matrix_sync(af[0], &qh[0][kk], 72);
        wmma::load_matrix_sync(af[1], &qh[16][kk], 72);
#pragma unroll
        for (int j = 0; j < 2; j++) {
            wmma::fragment<wmma::matrix_b, 16, 16, 16, __half, wmma::col_major> bf;
            wmma::load_matrix_sync(bf, &wk[wid * 32 + j * 16][kk], 72);
            wmma::mma_sync(cf[0][j], af[0], bf, cf[0][j]);
            wmma::mma_sync(cf[1][j], af[1], bf, cf[1][j]);
        }
    }
#pragma unroll
    for (int i = 0; i < 2; i++)
#pragma unroll
        for (int j = 0; j < 2; j++)
            wmma::store_matrix_sync(&outs[i * 16][wid * 32 + j * 16], cf[i][j], 132,
                                    wmma::mem_row_major);
    __syncthreads();
    for (int i = t; i < 32 * 128; i += 128) {
        int q = i >> 7, cl = i & 127;
        g_Qt[(size_t)(bh * NLQ + q) * NHS + c0 + cl] = __float2half_rn(outs[q][cl]);
    }
}

// ---------------- S = q~ @ X^T : wmma 64x64 tiles, 3-stage ----------------------
#define BM 128
#define BN 128
#define BK 32
#define LDK 40
#define SG_AS (BM * LDK)
#define SG_BS (BN * LDK)
#define SG_SMEM (3 * (SG_AS + SG_BS) * 2)   /* 61440 B */
__global__ void __launch_bounds__(128) sgemm()
{
    extern __shared__ __align__(16) __half dsm[];
    __half* As = dsm;
    __half* Bs = dsm + 3 * SG_AS;

    int b = blockIdx.z;
    int n0 = blockIdx.x * BN, m0 = blockIdx.y * BM;
    const __half* Ab = g_Qt + (size_t)b * 512 * NHS;
    const __half* Xb = g_Xh + (size_t)b * NLKV * NHS;
    float* Cb = g_S + (size_t)b * 512 * NLKV;

    int t = threadIdx.x, wid = t >> 5;
    int wm = wid & 1, wn = wid >> 1;

    wmma::fragment<wmma::accumulator, 16, 16, 16, float> cf[4][4];
#pragma unroll
    for (int i = 0; i < 4; i++)
#pragma unroll
        for (int j = 0; j < 4; j++) wmma::fill_fragment(cf[i][j], 0.f);

    auto load_stage = [&](int it, int buf) {
        int k0 = it * BK;
        __half* Ad = As + buf * SG_AS;
        __half* Bd = Bs + buf * SG_BS;
#pragma unroll
        for (int ch = t; ch < 512; ch += 128) {
            int r = ch >> 2, c = ch & 3;
            cp_async16(smem_u32(Ad + r * LDK + c * 8),
                       &Ab[(size_t)(m0 + r) * NHS + k0 + c * 8]);
        }
#pragma unroll
        for (int ch = t; ch < 512; ch += 128) {
            int r = ch >> 2, c = ch & 3;
            cp_async16(smem_u32(Bd + r * LDK + c * 8),
                       &Xb[(size_t)(n0 + r) * NHS + k0 + c * 8]);
        }
        CP_COMMIT();
    };

    const int NIT = NHS / BK;   // 32
    load_stage(0, 0);
    load_stage(1, 1);
    int buf = 0;
    for (int it = 0; it < NIT; it++) {
        CP_WAIT1();
        __syncthreads();
        if (it + 2 < NIT) {
            int nb = buf + 2; if (nb >= 3) nb -= 3;
            load_stage(it + 2, nb);
        }
        const __half* Ad = As + buf * SG_AS;
        const __half* Bd = Bs + buf * SG_BS;
#pragma unroll
        for (int kk = 0; kk < BK; kk += 16) {
            wmma::fragment<wmma::matrix_a, 16, 16, 16, __half, wmma::row_major> af[4];
#pragma unroll
            for (int i = 0; i < 4; i++)
                wmma::load_matrix_sync(af[i], Ad + (wm * 64 + i * 16) * LDK + kk, LDK);
#pragma unroll
            for (int j = 0; j < 4; j++) {
                wmma::fragment<wmma::matrix_b, 16, 16, 16, __half, wmma::col_major> bf;
                wmma::load_matrix_sync(bf, Bd + (wn * 64 + j * 16) * LDK + kk, LDK);
#pragma unroll
                for (int i = 0; i < 4; i++)
                    wmma::mma_sync(cf[i][j], af[i], bf, cf[i][j]);
            }
        }
        if (++buf == 3) buf = 0;
    }
#pragma unroll
    for (int i = 0; i < 4; i++)
#pragma unroll
        for (int j = 0; j < 4; j++)
            wmma::store_matrix_sync(
                &Cb[(size_t)(m0 + wm * 64 + i * 16) * NLKV + n0 + wn * 64 + j * 16],
                cf[i][j], NLKV, wmma::mem_row_major);
}

// ---------------- softmax rows of 4096: fp32 g_S -> fp16 g_P --------------------
__global__ void __launch_bounds__(256) softmax_rows()
{
    size_t m = blockIdx.x;
    const float4* row = reinterpret_cast<const float4*>(g_S + m * NLKV);
    __half2* prow = reinterpret_cast<__half2*>(g_P + m * NLKV);
    int t = threadIdx.x;
    __shared__ float red[8];

    float4 x[4];
    float mx = -1e30f;
#pragma unroll
    for (int i = 0; i < 4; i++) {
        x[i] = row[i * 256 + t];
        mx = fmaxf(fmaxf(fmaxf(mx, x[i].x), fmaxf(x[i].y, x[i].z)), x[i].w);
    }
#pragma unroll
    for (int o = 16; o > 0; o >>= 1)
        mx = fmaxf(mx, __shfl_xor_sync(0xffffffffu, mx, o));
    if ((t & 31) == 0) red[t >> 5] = mx;
    __syncthreads();
    if (t < 8) {
        float v = red[t];
#pragma unroll
        for (int o = 4; o > 0; o >>= 1) v = fmaxf(v, __shfl_xor_sync(0xffu, v, o));
        red[t] = v;
    }
    __syncthreads();
    mx = red[0];

    float s = 0.f;
#pragma unroll
    for (int i = 0; i < 4; i++) {
        x[i].x = __expf(x[i].x - mx); x[i].y = __expf(x[i].y - mx);
        x[i].z = __expf(x[i].z - mx); x[i].w = __expf(x[i].w - mx);
        s += (x[i].x + x[i].y) + (x[i].z + x[i].w);
    }
#pragma unroll
    for (int o = 16; o > 0; o >>= 1)
        s += __shfl_xor_sync(0xffffffffu, s, o);
    __syncthreads();
    if ((t & 31) == 0) red[t >> 5] = s;
    __syncthreads();
    if (t < 8) {
        float v = red[t];
#pragma unroll
        for (int o = 4; o > 0; o >>= 1) v += __shfl_xor_sync(0xffu, v, o);
        red[t] = v;
    }
    __syncthreads();
    float inv = 1.f / red[0];
#pragma unroll
    for (int i = 0; i < 4; i++) {
        prow[(i * 256 + t) * 2 + 0] = __floats2half2_rn(x[i].x * inv, x[i].y * inv);
        prow[(i * 256 + t) * 2 + 1] = __floats2half2_rn(x[i].z * inv, x[i].w * inv);
    }
}

// ---------------- Y = P @ X -> g_S (reused), wmma 64x64 tiles, 3-stage ----------
#define LDN 136
#define YG_AS (BM * LDK)
#define YG_BS (BK * LDN)
#define YG_SMEM (3 * (YG_AS + YG_BS) * 2)   /* 56832 B */
__global__ void __launch_bounds__(128) ygemm()
{
    extern __shared__ __align__(16) __half dsm[];
    __half* As = dsm;
    __half* Bs = dsm + 3 * YG_AS;

    int b = blockIdx.z;
    int n0 = blockIdx.x * BN, m0 = blockIdx.y * BM;
    const __half* Ab = g_P + (size_t)b * 512 * NLKV;
    const __half* Xb = g_Xh + (size_t)b * NLKV * NHS;
    float* Cb = g_S + (size_t)b * 512 * NHS;    // Y stored in g_S

    int t = threadIdx.x, wid = t >> 5;
    int wm = wid & 1, wn = wid >> 1;

    wmma::fragment<wmma::accumulator, 16, 16, 16, float> cf[4][4];
#pragma unroll
    for (int i = 0; i < 4; i++)
#pragma unroll
        for (int j = 0; j < 4; j++) wmma::fill_fragment(cf[i][j], 0.f);

    auto load_stage = [&](int it, int buf) {
        int k0 = it * BK;
        __half* Ad = As + buf * YG_AS;
        __half* Bd = Bs + buf * YG_BS;
#pragma unroll
        for (int ch = t; ch < 512; ch += 128) {
            int r = ch >> 2, c = ch & 3;
            cp_async16(smem_u32(Ad + r * LDK + c * 8),
                       &Ab[(size_t)(m0 + r) * NLKV + k0 + c * 8]);
        }
#pragma unroll
        for (int ch = t; ch < 512; ch += 128) {
            int r = ch >> 4, c = ch & 15;
            cp_async16(smem_u32(Bd + r * LDN + c * 8),
                       &Xb[(size_t)(k0 + r) * NHS + n0 + c * 8]);
        }
        CP_COMMIT();
    };

    const int NIT = NLKV / BK;   // 128
    load_stage(0, 0);
    load_stage(1, 1);
    int buf = 0;
    for (int it = 0; it < NIT; it++) {
        CP_WAIT1();
        __syncthreads();
        if (it + 2 < NIT) {
            int nb = buf + 2; if (nb >= 3) nb -= 3;
            load_stage(it + 2, nb);
        }
        const __half* Ad = As + buf * YG_AS;
        const __half* Bd = Bs + buf * YG_BS;
#pragma unroll
        for (int kk = 0; kk < BK; kk += 16) {
            wmma::fragment<wmma::matrix_a, 16, 16, 16, __half, wmma::row_major> af[4];
#pragma unroll
            for (int i = 0; i < 4; i++)
                wmma::load_matrix_sync(af[i], Ad + (wm * 64 + i * 16) * LDK + kk, LDK);
#pragma unroll
            for (int j = 0; j < 4; j++) {
                wmma::fragment<wmma::matrix_b, 16, 16, 16, __half, wmma::row_major> bf;
                wmma::load_matrix_sync(bf, Bd + kk * LDN + wn * 64 + j * 16, LDN);
#pragma unroll
                for (int i = 0; i < 4; i++)
                    wmma::mma_sync(cf[i][j], af[i], bf, cf[i][j]);
            }
        }
        if (++buf == 3) buf = 0;
    }
#pragma unroll
    for (int i = 0; i < 4; i++)
#pragma unroll
        for (int j = 0; j < 4; j++)
            wmma::store_matrix_sync(
                &Cb[(size_t)(m0 + wm * 64 + i * 16) * NHS + n0 + wn * 64 + j * 16],
                cf[i][j], NHS, wmma::mem_row_major);
}

// ---------------- vproj partials (reads Y from g_S), float4 loads ----------------
__global__ void __launch_bounds__(256) vproj_part(const float* __restrict__ Wv)
{
    int bh = blockIdx.x, b = bh >> 4, h = bh & 15;
    int ks = blockIdx.y;
    __shared__ float wvs[128][68];
    __shared__ float ys[32][132];
    int t = threadIdx.x;
    int d = t & 63, qg = t >> 6;
    float acc[8];
#pragma unroll
    for (int j = 0; j < 8; j++) acc[j] = 0.f;

#pragma unroll
    for (int half = 0; half < 2; half++) {
        int c0 = ks * 256 + half * 128;
        __syncthreads();
        // Wv: 128 rows x 64 cols, float4 (rows of Wv are NHS-strided; head cols contiguous)
        for (int i = t; i < 128 * 16; i += 256) {
            int r = i >> 4, dd = (i & 15) * 4;
            float4 v = *reinterpret_cast<const float4*>(
                &Wv[(size_t)(c0 + r) * NHS + h * ND + dd]);
            *reinterpret_cast<float4*>(&wvs[r][dd]) = v;
        }
        // Y: 32 rows x 128 cols, float4
        for (int i = t; i < 32 * 32; i += 256) {
            int q = i >> 5, cl = (i & 31) * 4;
            float4 v = *reinterpret_cast<const float4*>(
                &g_S[(size_t)(bh * NLQ + q) * NHS + c0 + cl]);
            *reinterpret_cast<float4*>(&ys[q][cl]) = v;
        }
        __syncthreads();
#pragma unroll 4
        for (int c = 0; c < 128; c++) {
            float w = wvs[c][d];
#pragma unroll
            for (int j = 0; j < 8; j++) acc[j] += ys[qg * 8 + j][c] * w;
        }
    }
#pragma unroll
    for (int j = 0; j < 8; j++)
        g_qpart[((size_t)ks * MQ + b * NLQ + qg * 8 + j) * NHS + h * ND + d] = acc[j];
}

// ---------------- oproj partial (sums vproj partials), k-split 8 ----------------
__global__ void __launch_bounds__(256) oproj_part(const float* __restrict__ W)
{
    int c0 = blockIdx.x * 256, r0 = blockIdx.y * 32, ks = blockIdx.z;
    __shared__ float xs[32][128];
    int t = threadIdx.x;
    for (int i = t; i < 32 * 128; i += 256) {
        int r = i >> 7, kk = i & 127;
        size_t base = (size_t)(r0 + r) * NHS + ks * 128 + kk;
        float s = 0.f;
#pragma unroll
        for (int s2 = 0; s2 < VSPL; s2++)
            s += g_qpart[(size_t)s2 * MQ * NHS + base];
        xs[r][kk] = s;
    }
    __syncthreads();
    float acc[32];
#pragma unroll
    for (int r = 0; r < 32; r++) acc[r] = 0.f;
    int c = c0 + t;
    const float* Wc = W + (size_t)(ks * 128) * NHS + c;
    for (int k = 0; k < 128; k += 4) {
        float w0 = Wc[(size_t)(k+0) * NHS];
        float w1 = Wc[(size_t)(k+1) * NHS];
        float w2 = Wc[(size_t)(k+2) * NHS];
        float w3 = Wc[(size_t)(k+3) * NHS];
#pragma unroll
        for (int r = 0; r < 32; r++) {
            float4 xv = *reinterpret_cast<const float4*>(&xs[r][k]);
            acc[r] += xv.x * w0 + xv.y * w1 + xv.z * w2 + xv.w * w3;
        }
    }
#pragma unroll
    for (int r = 0; r < 32; r++)
        g_opart[((size_t)ks * MQ + r0 + r) * NHS + c] = acc[r];
}

__global__ void __launch_bounds__(256) oreduce(float* __restrict__ Y)
{
    int i = blockIdx.x * 256 + threadIdx.x;
    float s = 0.f;
#pragma unroll
    for (int ks = 0; ks < OSPL; ks++)
        s += g_opart[(size_t)ks * MQ * NHS + i];
    Y[i] = s;
}

// ================= launcher =======================================================
extern "C" void kernel_launch(void* const* d_in, const int* in_sizes, int n_in,
                              void* d_out, int out_size)
{
    const float* hidden = (const float*)d_in[0];
    const float* enc    = (const float*)d_in[1];
    const int*   pos32  = (const int*)d_in[2];
    const float* Wq     = (const float*)d_in[3];
    const float* Wk     = (const float*)d_in[4];
    const float* Wv     = (const float*)d_in[5];
    const float* Wo     = (const float*)d_in[6];
    float*       out    = (float*)d_out;

    cudaFuncSetAttribute(sgemm, cudaFuncAttributeMaxDynamicSharedMemorySize, SG_SMEM);
    cudaFuncSetAttribute(ygemm, cudaFuncAttributeMaxDynamicSharedMemorySize, YG_SMEM);

    // 1) fused: encoder->fp16 (2 f4/thread) + qproj partials (k-split 8)
    prep<<<256 + MKV * NHS / 8 / 256, 256>>>(enc, hidden, Wq);

    // 2) RoPE reduce
    rope_reduce<<<MQ, 256>>>(pos32);

    // 3) fold Wk into q (wmma)
    qtilde<<<dim3(NB * NH, 8), 128>>>(Wk);

    // 4) S = q~ @ X^T -> fp32 g_S   (profiled slot)
    sgemm<<<dim3(NLKV / BN, 4, NB), 128, SG_SMEM>>>();

    // 5) softmax: fp32 -> fp16 g_P
    softmax_rows<<<MR, 256>>>();

    // 6) Y = P @ X -> g_S
    ygemm<<<dim3(NHS / BN, 4, NB), 128, YG_SMEM>>>();

    // 7) fold Wv (partials into g_qpart)
    vproj_part<<<dim3(NB * NH, VSPL), 256>>>(Wv);

    // 8) output projection (k-split 8)
    oproj_part<<<dim3(4, 8, OSPL), 256>>>(Wo);
    oreduce<<<(MQ * NHS) / 256, 256>>>(out);
}